// round 2
// baseline (speedup 1.0000x reference)
#include <cuda_runtime.h>

// Problem constants
#define NIMG 16384
#define IMG_PER_CTA 8
#define GRID_BIG (NIMG / IMG_PER_CTA)   // 2048 CTAs

// Layer shapes:
//  x:  [B,1,16,16]
//  h1: conv 3x3 -> [B,16,14,14]   (stored position-major: [img][196][16])
//  h2: conv 2x2 -> [B,32,13,13]   (stored position-major: [img][169][32])
//  h3: conv 1x1 -> [B,64,13,13]   (never materialized)
//  out: [B,10]

// ---------------- scratch (device globals; no allocs allowed) ----------------
__device__ float g_h1[(size_t)NIMG * 196 * 16];   // 205 MB
__device__ float g_h2[(size_t)NIMG * 169 * 32];   // 354 MB
__device__ float g_s1[32];    // sum[16], sumsq[16]
__device__ float g_s2[64];    // sum[32], sumsq[32]
__device__ float g_s3[128];   // sum[64], sumsq[64]
__device__ float g_bn1[32];   // scale[16], bias[16]
__device__ float g_bn2[64];   // scale[32], bias[32]
__device__ float g_bn3[128];  // scale[64], bias[64]

// ---------------- zero the stat accumulators every launch ----------------
__global__ void k_zero() {
    int t = threadIdx.x;
    if (t < 32)  g_s1[t] = 0.f;
    if (t < 64)  g_s2[t] = 0.f;
    if (t < 128) g_s3[t] = 0.f;
}

// ---------------- conv1 (3x3) + stats1 ----------------
__global__ __launch_bounds__(256) void k_conv1(const float* __restrict__ x,
                                               const float* __restrict__ w1) {
    __shared__ float s_w[144];     // [16][3][3]
    __shared__ float s_in[256];    // 16x16 image
    __shared__ float s_red[256];
    int t = threadIdx.x;
    if (t < 144) s_w[t] = w1[t];
    int c = t & 15;        // output channel owned by this thread
    int chunk = t >> 4;    // position strip
    float ls = 0.f, lsq = 0.f;
    int img0 = blockIdx.x * IMG_PER_CTA;

    for (int ii = 0; ii < IMG_PER_CTA; ii++) {
        __syncthreads();
        s_in[t] = x[(size_t)(img0 + ii) * 256 + t];
        __syncthreads();
        const float* wc = &s_w[c * 9];
        float w00 = wc[0], w01 = wc[1], w02 = wc[2];
        float w10 = wc[3], w11 = wc[4], w12 = wc[5];
        float w20 = wc[6], w21 = wc[7], w22 = wc[8];
        for (int p = chunk; p < 196; p += 16) {
            int y = p / 14, xx = p - y * 14;
            const float* r0 = &s_in[y * 16 + xx];
            float acc = r0[0]  * w00 + r0[1]  * w01 + r0[2]  * w02
                      + r0[16] * w10 + r0[17] * w11 + r0[18] * w12
                      + r0[32] * w20 + r0[33] * w21 + r0[34] * w22;
            g_h1[((size_t)(img0 + ii) * 196 + p) * 16 + c] = acc;  // coalesced (c = lane)
            ls += acc; lsq += acc * acc;
        }
    }
    __syncthreads();
    s_red[c * 16 + chunk] = ls;
    __syncthreads();
    if (t < 16) { float s = 0.f; for (int j = 0; j < 16; j++) s += s_red[t * 16 + j];
                  atomicAdd(&g_s1[t], s); }
    __syncthreads();
    s_red[c * 16 + chunk] = lsq;
    __syncthreads();
    if (t < 16) { float s = 0.f; for (int j = 0; j < 16; j++) s += s_red[t * 16 + j];
                  atomicAdd(&g_s1[16 + t], s); }
}

// ---------------- finalize BN params (scale/bias) ----------------
__global__ void k_finalize(int which, const float* __restrict__ gamma,
                           const float* __restrict__ beta) {
    int C       = (which == 0) ? 16 : (which == 1) ? 32 : 64;
    float* s    = (which == 0) ? g_s1 : (which == 1) ? g_s2 : g_s3;
    float* bn   = (which == 0) ? g_bn1 : (which == 1) ? g_bn2 : g_bn3;
    float n     = (which == 0) ? (16384.f * 196.f) : (16384.f * 169.f);
    int t = threadIdx.x;
    if (t < C) {
        float mean = s[t] / n;
        float var  = s[C + t] / n - mean * mean;
        float sc   = gamma[t] * rsqrtf(var + 1e-5f);
        bn[t]      = sc;
        bn[C + t]  = beta[t] - mean * sc;
    }
}

// ---------------- bn1+relu -> conv2 (2x2) + stats2 ----------------
__global__ __launch_bounds__(256) void k_conv2(const float* __restrict__ w2) {
    __shared__ float s_a[3136];    // a1 [196][16]
    __shared__ float s_w[2048];    // [c1*4+q][c2]  (channel-last: lanes conflict-free)
    __shared__ float s_bn[32];
    __shared__ float s_red[256];
    int t = threadIdx.x;
    for (int i = t; i < 2048; i += 256) {
        int c2 = i >> 6, r = i & 63;       // src [c2][c1][ky][kx]
        s_w[r * 32 + c2] = w2[i];
    }
    if (t < 32) s_bn[t] = g_bn1[t];
    int c2 = t & 31, chunk = t >> 5;
    float ls = 0.f, lsq = 0.f;
    int img0 = blockIdx.x * IMG_PER_CTA;

    for (int ii = 0; ii < IMG_PER_CTA; ii++) {
        __syncthreads();
        const float* src = &g_h1[(size_t)(img0 + ii) * 3136];
        for (int i = t; i < 3136; i += 256) {
            int c = i & 15;
            float v = src[i] * s_bn[c] + s_bn[16 + c];
            s_a[i] = v > 0.f ? v : 0.f;
        }
        __syncthreads();
        float* dst = &g_h2[(size_t)(img0 + ii) * 5408];
        for (int p = chunk; p < 169; p += 8) {
            int y = p / 13, xx = p - y * 13;
            int r0 = (y * 14 + xx) * 16;
            float acc = 0.f;
#pragma unroll
            for (int c1 = 0; c1 < 16; c1++) {
                float a00 = s_a[r0 + c1],       a01 = s_a[r0 + 16 + c1];
                float a10 = s_a[r0 + 224 + c1], a11 = s_a[r0 + 240 + c1];
                acc += a00 * s_w[(c1 * 4 + 0) * 32 + c2]
                     + a01 * s_w[(c1 * 4 + 1) * 32 + c2]
                     + a10 * s_w[(c1 * 4 + 2) * 32 + c2]
                     + a11 * s_w[(c1 * 4 + 3) * 32 + c2];
            }
            dst[p * 32 + c2] = acc;   // coalesced (c2 = lane)
            ls += acc; lsq += acc * acc;
        }
    }
    __syncthreads();
    s_red[c2 * 8 + chunk] = ls;
    __syncthreads();
    if (t < 32) { float s = 0.f; for (int j = 0; j < 8; j++) s += s_red[t * 8 + j];
                  atomicAdd(&g_s2[t], s); }
    __syncthreads();
    s_red[c2 * 8 + chunk] = lsq;
    __syncthreads();
    if (t < 32) { float s = 0.f; for (int j = 0; j < 8; j++) s += s_red[t * 8 + j];
                  atomicAdd(&g_s2[32 + t], s); }
}

// ---------------- bn2+relu -> conv3 (1x1) stats only (h3 discarded) ----------------
__global__ __launch_bounds__(256) void k_stats3(const float* __restrict__ w3) {
    __shared__ float s_a[5408];    // a2 [169][32]
    __shared__ float s_w[2048];    // [k][c3]
    __shared__ float s_bn[64];
    __shared__ float s_red[256];
    int t = threadIdx.x;
    for (int i = t; i < 2048; i += 256) { int c3 = i >> 5, k = i & 31; s_w[k * 64 + c3] = w3[i]; }
    if (t < 64) s_bn[t] = g_bn2[t];
    int c3 = t & 63, chunk = t >> 6;
    float ls = 0.f, lsq = 0.f;
    int img0 = blockIdx.x * IMG_PER_CTA;

    for (int ii = 0; ii < IMG_PER_CTA; ii++) {
        __syncthreads();
        const float* src = &g_h2[(size_t)(img0 + ii) * 5408];
        for (int i = t; i < 5408; i += 256) {
            int c = i & 31;
            float v = src[i] * s_bn[c] + s_bn[32 + c];
            s_a[i] = v > 0.f ? v : 0.f;
        }
        __syncthreads();
        for (int p = chunk; p < 169; p += 4) {
            const float* ap = &s_a[p * 32];
            float acc = 0.f;
#pragma unroll
            for (int k = 0; k < 32; k++) acc += ap[k] * s_w[k * 64 + c3];
            ls += acc; lsq += acc * acc;
        }
    }
    __syncthreads();
    s_red[c3 * 4 + chunk] = ls;
    __syncthreads();
    if (t < 64) { float s = s_red[t*4] + s_red[t*4+1] + s_red[t*4+2] + s_red[t*4+3];
                  atomicAdd(&g_s3[t], s); }
    __syncthreads();
    s_red[c3 * 4 + chunk] = lsq;
    __syncthreads();
    if (t < 64) { float s = s_red[t*4] + s_red[t*4+1] + s_red[t*4+2] + s_red[t*4+3];
                  atomicAdd(&g_s3[64 + t], s); }
}

// ---------------- bn2+relu -> conv3 -> bn3+relu -> fc, fused ----------------
// Dynamic smem: a2 for 8 images so each fc_w element is reused 8x (L2-friendly).
__global__ __launch_bounds__(256) void k_final(const float* __restrict__ w3,
                                               const float* __restrict__ fc_w,
                                               const float* __restrict__ fc_b,
                                               float* __restrict__ out) {
    extern __shared__ float sm[];
    float* s_a   = sm;                // 8*5408 = 43264
    float* s_w   = sm + 43264;        // 2048
    float* s_bn2 = s_w + 2048;        // 64
    float* s_bn3 = s_bn2 + 64;        // 128
    float* s_out = s_bn3 + 128;       // 80
    int t = threadIdx.x;
    for (int i = t; i < 2048; i += 256) { int c3 = i >> 5, k = i & 31; s_w[k * 64 + c3] = w3[i]; }
    if (t < 64)  s_bn2[t] = g_bn2[t];
    if (t < 128) s_bn3[t] = g_bn3[t];
    if (t < 80)  s_out[t] = 0.f;
    int img0 = blockIdx.x * IMG_PER_CTA;
    const float* src = &g_h2[(size_t)img0 * 5408];
    __syncthreads();
    for (int i = t; i < 8 * 5408; i += 256) {
        int c = i & 31;
        float v = src[i] * s_bn2[c] + s_bn2[32 + c];
        s_a[i] = v > 0.f ? v : 0.f;
    }
    __syncthreads();

    int c3 = t & 63, grp = t >> 6;        // 4 groups x 2 images each
    float sc3 = s_bn3[c3], bi3 = s_bn3[64 + c3];
    float o0[10], o1[10];
#pragma unroll
    for (int j = 0; j < 10; j++) { o0[j] = 0.f; o1[j] = 0.f; }
    const float* a0 = &s_a[(grp * 2 + 0) * 5408];
    const float* a1 = &s_a[(grp * 2 + 1) * 5408];

    for (int p = 0; p < 169; p++) {
        float acc0 = 0.f, acc1 = 0.f;
#pragma unroll
        for (int k = 0; k < 32; k++) {
            float w = s_w[k * 64 + c3];
            acc0 += a0[p * 32 + k] * w;
            acc1 += a1[p * 32 + k] * w;
        }
        float v0 = acc0 * sc3 + bi3; v0 = v0 > 0.f ? v0 : 0.f;
        float v1 = acc1 * sc3 + bi3; v1 = v1 > 0.f ? v1 : 0.f;
        const float* fw = &fc_w[c3 * 169 + p];
#pragma unroll
        for (int j = 0; j < 10; j++) {
            float w = fw[(size_t)j * 10816];
            o0[j] += v0 * w;
            o1[j] += v1 * w;
        }
    }
#pragma unroll
    for (int j = 0; j < 10; j++) {
        atomicAdd(&s_out[(grp * 2 + 0) * 10 + j], o0[j]);
        atomicAdd(&s_out[(grp * 2 + 1) * 10 + j], o1[j]);
    }
    __syncthreads();
    if (t < 80) {
        int im = t / 10, j = t - im * 10;
        out[(size_t)(img0 + im) * 10 + j] = s_out[t] + fc_b[j];
    }
}

// ---------------- launch ----------------
extern "C" void kernel_launch(void* const* d_in, const int* in_sizes, int n_in,
                              void* d_out, int out_size) {
    const float* x    = (const float*)d_in[0];
    const float* w1   = (const float*)d_in[1];
    const float* w2   = (const float*)d_in[2];
    const float* w3   = (const float*)d_in[3];
    const float* g1   = (const float*)d_in[4];
    const float* b1   = (const float*)d_in[5];
    const float* g2   = (const float*)d_in[6];
    const float* b2   = (const float*)d_in[7];
    const float* g3   = (const float*)d_in[8];
    const float* b3   = (const float*)d_in[9];
    const float* fc_w = (const float*)d_in[10];
    const float* fc_b = (const float*)d_in[11];
    float* out = (float*)d_out;

    // 45584 floats = 182336 bytes of dynamic smem for k_final
    cudaFuncSetAttribute(k_final, cudaFuncAttributeMaxDynamicSharedMemorySize, 182336);

    k_zero<<<1, 128>>>();
    k_conv1<<<GRID_BIG, 256>>>(x, w1);
    k_finalize<<<1, 64>>>(0, g1, b1);
    k_conv2<<<GRID_BIG, 256>>>(w2);
    k_finalize<<<1, 64>>>(1, g2, b2);
    k_stats3<<<GRID_BIG, 256>>>(w3);
    k_finalize<<<1, 64>>>(2, g3, b3);
    k_final<<<GRID_BIG, 256, 182336>>>(w3, fc_w, fc_b, out);
}

// round 3
// speedup vs baseline: 1.0744x; 1.0744x over previous
#include <cuda_runtime.h>

#define NIMG 16384
#define NPAIR (NIMG/2)          // 8192 image pairs

// Layouts (pair-interleaved, position-major):
//  g_h1: [pair][196][16][2]   (205 MB)
//  g_h2: [pair][169][32][2]   (354 MB)

__device__ float g_h1[(size_t)NPAIR * 196 * 16 * 2];
__device__ float g_h2[(size_t)NPAIR * 169 * 32 * 2];
__device__ float g_s1[32];      // sum[16], sumsq[16]
__device__ float g_s2[64];      // sum[32], sumsq[32]
__device__ float g_gram[1024];  // M[32][32]
__device__ float g_sumA[32];    // A[k]
__device__ float g_bn1[32];
__device__ float g_bn2[64];
__device__ float g_bn3[128];

// ---------------- f32x2 helpers ----------------
__device__ __forceinline__ unsigned long long pk2(float a, float b) {
    unsigned long long r;
    asm("mov.b64 %0, {%1, %2};" : "=l"(r) : "f"(a), "f"(b));
    return r;
}
__device__ __forceinline__ void upk2(unsigned long long v, float& a, float& b) {
    asm("mov.b64 {%0, %1}, %2;" : "=f"(a), "=f"(b) : "l"(v));
}
#define FMA2(d, a, b) asm("fma.rn.f32x2 %0, %1, %2, %0;" : "+l"(d) : "l"(a), "l"(b))

// ---------------- zero accumulators ----------------
__global__ void k_zero() {
    int t = threadIdx.x;
    g_gram[t] = 0.f;            // 1024 threads
    if (t < 32) { g_s1[t] = 0.f; g_sumA[t] = 0.f; }
    if (t < 64) g_s2[t] = 0.f;
}

// ---------------- conv1 (3x3) + stats1; output pair-packed ----------------
__global__ __launch_bounds__(256) void k_conv1(const float* __restrict__ x,
                                               const float* __restrict__ w1) {
    __shared__ float s_w[144];
    __shared__ float s_in[512];     // one image pair
    __shared__ float s_red[256];
    int t = threadIdx.x;
    if (t < 144) s_w[t] = w1[t];
    int c = t & 15, sel = (t >> 4) & 1, chunk = t >> 5;   // 8 chunks
    __syncthreads();
    const float* wc = &s_w[c * 9];
    float w00 = wc[0], w01 = wc[1], w02 = wc[2];
    float w10 = wc[3], w11 = wc[4], w12 = wc[5];
    float w20 = wc[6], w21 = wc[7], w22 = wc[8];
    float ls = 0.f, lsq = 0.f;
    int pair0 = blockIdx.x * 4;

    for (int pp = 0; pp < 4; pp++) {
        int pair = pair0 + pp;
        __syncthreads();
        const float* xp = x + (size_t)pair * 512;
        s_in[t] = xp[t];
        s_in[256 + t] = xp[256 + t];
        __syncthreads();
        const float* img = &s_in[sel * 256];
        float* dst = &g_h1[(size_t)pair * 6272];
        for (int p = chunk; p < 196; p += 8) {
            int y = p / 14, xx = p - y * 14;
            const float* r0 = &img[y * 16 + xx];
            float acc = r0[0]  * w00 + r0[1]  * w01 + r0[2]  * w02
                      + r0[16] * w10 + r0[17] * w11 + r0[18] * w12
                      + r0[32] * w20 + r0[33] * w21 + r0[34] * w22;
            dst[p * 32 + c * 2 + sel] = acc;    // coalesced within warp
            ls += acc; lsq += acc * acc;
        }
    }
    __syncthreads();
    s_red[t] = ls;
    __syncthreads();
    if (t < 16) { float s = 0.f; for (int j = 0; j < 16; j++) s += s_red[t + 16 * j];
                  atomicAdd(&g_s1[t], s); }
    __syncthreads();
    s_red[t] = lsq;
    __syncthreads();
    if (t < 16) { float s = 0.f; for (int j = 0; j < 16; j++) s += s_red[t + 16 * j];
                  atomicAdd(&g_s1[16 + t], s); }
}

// ---------------- BN params for layers 1,2 ----------------
__global__ void k_finalize(int which, const float* __restrict__ gamma,
                           const float* __restrict__ beta) {
    int C     = (which == 0) ? 16 : 32;
    float* s  = (which == 0) ? g_s1 : g_s2;
    float* bn = (which == 0) ? g_bn1 : g_bn2;
    float n   = (which == 0) ? (16384.f * 196.f) : (16384.f * 169.f);
    int t = threadIdx.x;
    if (t < C) {
        float mean = s[t] / n;
        float var  = s[C + t] / n - mean * mean;
        float sc   = gamma[t] * rsqrtf(var + 1e-5f);
        bn[t] = sc;
        bn[C + t] = beta[t] - mean * sc;
    }
}

// ---------------- bn1+relu -> conv2 (2x2) + stats2 ----------------
// Weights in registers; a pair-packed in smem; both images per thread (2 acc chains).
__global__ __launch_bounds__(256) void k_conv2(const float* __restrict__ w2) {
    __shared__ __align__(16) float s_a[196 * 32];   // one pair, [196][16][2]
    __shared__ float s_red[256];
    __shared__ float s_bn[32];
    int t = threadIdx.x;
    if (t < 32) s_bn[t] = g_bn1[t];
    int c2 = t & 31, chunk = t >> 5;   // 8 chunks over 169 positions
    // load this thread's 64 weights: w2 layout [c2][c1][ky][kx] contiguous per c2
    float w[64];
    const float4* wsrc = reinterpret_cast<const float4*>(w2) + c2 * 16;
#pragma unroll
    for (int i = 0; i < 16; i++) {
        float4 v = wsrc[i];
        w[4 * i] = v.x; w[4 * i + 1] = v.y; w[4 * i + 2] = v.z; w[4 * i + 3] = v.w;
    }
    float ls = 0.f, lsq = 0.f;
    int pair0 = blockIdx.x * 4;

    for (int pp = 0; pp < 4; pp++) {
        int pair = pair0 + pp;
        __syncthreads();
        const float* src = &g_h1[(size_t)pair * 6272];
        for (int i = t; i < 6272; i += 256) {
            int c = (i >> 1) & 15;
            float v = src[i] * s_bn[c] + s_bn[16 + c];
            s_a[i] = v > 0.f ? v : 0.f;
        }
        __syncthreads();
        float2* dst = reinterpret_cast<float2*>(&g_h2[(size_t)pair * 10816]);
        for (int p = chunk; p < 169; p += 8) {
            int y = p / 13, xx = p - y * 13;
            const float4* r0 = reinterpret_cast<const float4*>(s_a) + (y * 14 + xx) * 8;
            const float4* r1 = r0 + 112;   // next row (+14 positions * 8 float4)
            float a0 = 0.f, a1 = 0.f;
#pragma unroll
            for (int j = 0; j < 16; j++) {     // ky = 0
                float4 v = r0[j];
                int c1 = (2 * j) & 15, kx = j >> 3;
                float wa = w[c1 * 4 + kx], wb = w[(c1 + 1) * 4 + kx];
                a0 += v.x * wa; a1 += v.y * wa;
                a0 += v.z * wb; a1 += v.w * wb;
            }
#pragma unroll
            for (int j = 0; j < 16; j++) {     // ky = 1
                float4 v = r1[j];
                int c1 = (2 * j) & 15, kx = j >> 3;
                float wa = w[c1 * 4 + 2 + kx], wb = w[(c1 + 1) * 4 + 2 + kx];
                a0 += v.x * wa; a1 += v.y * wa;
                a0 += v.z * wb; a1 += v.w * wb;
            }
            dst[p * 32 + c2] = make_float2(a0, a1);   // pair-packed, coalesced
            ls += a0 + a1; lsq += a0 * a0 + a1 * a1;
        }
    }
    __syncthreads();
    s_red[t] = ls;
    __syncthreads();
    if (t < 32) { float s = 0.f; for (int j = 0; j < 8; j++) s += s_red[t + 32 * j];
                  atomicAdd(&g_s2[t], s); }
    __syncthreads();
    s_red[t] = lsq;
    __syncthreads();
    if (t < 32) { float s = 0.f; for (int j = 0; j < 8; j++) s += s_red[t + 32 * j];
                  atomicAdd(&g_s2[32 + t], s); }
}

// ---------------- bn2+relu -> Gram matrix of a2 (replaces conv3 recompute) ----------------
__global__ __launch_bounds__(256) void k_gram() {
    __shared__ __align__(16) float s_a[169 * 64];   // one pair, [169][32][2]
    __shared__ float s_bn[64];
    int t = threadIdx.x;
    if (t < 64) s_bn[t] = g_bn2[t];
    int k = t & 31, w8 = t >> 5;         // this thread: row k, cols w8*4 .. w8*4+3
    int kpb = w8 * 4;
    unsigned long long acc0 = pk2(0.f, 0.f), acc1 = acc0, acc2 = acc0, acc3 = acc0;
    unsigned long long sA = acc0;
    const unsigned long long one2 = pk2(1.f, 1.f);
    int pair0 = blockIdx.x * 4;

    for (int pp = 0; pp < 4; pp++) {
        __syncthreads();
        const float* src = &g_h2[(size_t)(pair0 + pp) * 10816];
        for (int i = t; i < 10816; i += 256) {
            int c = (i >> 1) & 31;
            float v = src[i] * s_bn[c] + s_bn[32 + c];
            s_a[i] = v > 0.f ? v : 0.f;
        }
        __syncthreads();
        const unsigned long long* ap = reinterpret_cast<const unsigned long long*>(s_a);
        for (int p = 0; p < 169; p++) {
            unsigned long long ak = ap[p * 32 + k];
            if (w8 == 0) FMA2(sA, ak, one2);
            unsigned long long b0 = ap[p * 32 + kpb];
            unsigned long long b1 = ap[p * 32 + kpb + 1];
            unsigned long long b2 = ap[p * 32 + kpb + 2];
            unsigned long long b3 = ap[p * 32 + kpb + 3];
            FMA2(acc0, ak, b0); FMA2(acc1, ak, b1);
            FMA2(acc2, ak, b2); FMA2(acc3, ak, b3);
        }
    }
    float lo, hi;
    upk2(acc0, lo, hi); atomicAdd(&g_gram[k * 32 + kpb],     lo + hi);
    upk2(acc1, lo, hi); atomicAdd(&g_gram[k * 32 + kpb + 1], lo + hi);
    upk2(acc2, lo, hi); atomicAdd(&g_gram[k * 32 + kpb + 2], lo + hi);
    upk2(acc3, lo, hi); atomicAdd(&g_gram[k * 32 + kpb + 3], lo + hi);
    if (w8 == 0) { upk2(sA, lo, hi); atomicAdd(&g_sumA[k], lo + hi); }
}

// ---------------- bn3 params from Gram: S1 = w.A, S2 = w M w^T ----------------
__global__ void k_fin3(const float* __restrict__ w3, const float* __restrict__ gamma,
                       const float* __restrict__ beta) {
    __shared__ float s_m[1024];
    __shared__ float s_A[32];
    __shared__ float s_w[64 * 33];
    int t = threadIdx.x;    // 64 threads, one c3 each
    for (int i = t; i < 1024; i += 64) s_m[i] = g_gram[i];
    if (t < 32) s_A[t] = g_sumA[t];
    for (int kk = 0; kk < 32; kk++) s_w[t * 33 + kk] = w3[t * 32 + kk];
    __syncthreads();
    float S1 = 0.f, S2 = 0.f;
    for (int k = 0; k < 32; k++) {
        float wk = s_w[t * 33 + k];
        S1 += wk * s_A[k];
        float inner = 0.f;
        for (int kp = 0; kp < 32; kp++) inner += s_w[t * 33 + kp] * s_m[k * 32 + kp];
        S2 += wk * inner;
    }
    float n = 16384.f * 169.f;
    float mean = S1 / n;
    float var  = S2 / n - mean * mean;
    float sc   = gamma[t] * rsqrtf(var + 1e-5f);
    g_bn3[t] = sc;
    g_bn3[64 + t] = beta[t] - mean * sc;
}

// ---------------- bn2+relu -> conv3 (f32x2) -> bn3+relu -> fc ----------------
// 2 pairs (4 images) per CTA; w3 duplicated-packed in 64 regs; fc via L1-cached LDG.
__global__ __launch_bounds__(256) void k_final(const float* __restrict__ w3,
                                               const float* __restrict__ fc_w,
                                               const float* __restrict__ fc_b,
                                               float* __restrict__ out) {
    extern __shared__ __align__(16) float s_a[];    // 2 pairs x 10816 floats
    __shared__ float s_bn2[64];
    __shared__ float s_bn3[128];
    __shared__ float s_out[48];
    int t = threadIdx.x;
    int c3 = t & 63, pairsel = (t >> 6) & 1, ph = t >> 7;
    if (t < 64)  s_bn2[t] = g_bn2[t];
    if (t < 128) s_bn3[t] = g_bn3[t];
    if (t < 48)  s_out[t] = 0.f;
    // duplicated-packed w3 row in registers (32 x 64-bit)
    unsigned long long wp[32];
    {
        const float4* ws = reinterpret_cast<const float4*>(w3) + c3 * 8;
#pragma unroll
        for (int i = 0; i < 8; i++) {
            float4 v = ws[i];
            wp[4 * i]     = pk2(v.x, v.x);
            wp[4 * i + 1] = pk2(v.y, v.y);
            wp[4 * i + 2] = pk2(v.z, v.z);
            wp[4 * i + 3] = pk2(v.w, v.w);
        }
    }
    size_t base = (size_t)blockIdx.x * 2 * 10816;
    __syncthreads();
    for (int i = t; i < 2 * 10816; i += 256) {
        int c = (i >> 1) & 31;
        float v = g_h2[base + i] * s_bn2[c] + s_bn2[32 + c];
        s_a[i] = v > 0.f ? v : 0.f;
    }
    __syncthreads();

    float sc3 = s_bn3[c3], bi3 = s_bn3[64 + c3];
    float o0[10], o1[10];
#pragma unroll
    for (int j = 0; j < 10; j++) { o0[j] = 0.f; o1[j] = 0.f; }
    const float* sap = s_a + pairsel * 10816;
    int p_beg = ph ? 85 : 0, p_end = ph ? 169 : 85;

    for (int p = p_beg; p < p_end; p++) {
        const ulonglong2* row =
            reinterpret_cast<const ulonglong2*>(sap) + p * 16;
        unsigned long long acc = pk2(0.f, 0.f);
#pragma unroll
        for (int kk = 0; kk < 16; kk++) {
            ulonglong2 v = row[kk];
            FMA2(acc, v.x, wp[2 * kk]);
            FMA2(acc, v.y, wp[2 * kk + 1]);
        }
        float h0, h1;
        upk2(acc, h0, h1);
        float v0 = fmaxf(fmaf(h0, sc3, bi3), 0.f);
        float v1 = fmaxf(fmaf(h1, sc3, bi3), 0.f);
        const float* fw = &fc_w[c3 * 169 + p];
#pragma unroll
        for (int j = 0; j < 10; j++) {
            float w = fw[(size_t)j * 10816];
            o0[j] += v0 * w;
            o1[j] += v1 * w;
        }
    }
    // warp shuffle reduce (lanes within a warp share pairsel/ph, differ in c3)
#pragma unroll
    for (int j = 0; j < 10; j++) {
#pragma unroll
        for (int off = 16; off > 0; off >>= 1) {
            o0[j] += __shfl_xor_sync(0xffffffffu, o0[j], off);
            o1[j] += __shfl_xor_sync(0xffffffffu, o1[j], off);
        }
    }
    if ((t & 31) == 0) {
#pragma unroll
        for (int j = 0; j < 10; j++) {
            atomicAdd(&s_out[pairsel * 20 + j],      o0[j]);
            atomicAdd(&s_out[pairsel * 20 + 10 + j], o1[j]);
        }
    }
    __syncthreads();
    if (t < 40) {
        int im = t / 10, j = t - im * 10;
        out[(size_t)(blockIdx.x * 4 + im) * 10 + j] = s_out[im * 10 + j] + fc_b[j];
    }
}

// ---------------- launch ----------------
extern "C" void kernel_launch(void* const* d_in, const int* in_sizes, int n_in,
                              void* d_out, int out_size) {
    const float* x    = (const float*)d_in[0];
    const float* w1   = (const float*)d_in[1];
    const float* w2   = (const float*)d_in[2];
    const float* w3   = (const float*)d_in[3];
    const float* g1   = (const float*)d_in[4];
    const float* b1   = (const float*)d_in[5];
    const float* g2   = (const float*)d_in[6];
    const float* b2   = (const float*)d_in[7];
    const float* g3   = (const float*)d_in[8];
    const float* b3   = (const float*)d_in[9];
    const float* fc_w = (const float*)d_in[10];
    const float* fc_b = (const float*)d_in[11];
    float* out = (float*)d_out;

    cudaFuncSetAttribute(k_final, cudaFuncAttributeMaxDynamicSharedMemorySize, 2 * 10816 * 4);

    k_zero<<<1, 1024>>>();
    k_conv1<<<2048, 256>>>(x, w1);
    k_finalize<<<1, 64>>>(0, g1, b1);
    k_conv2<<<2048, 256>>>(w2);
    k_finalize<<<1, 64>>>(1, g2, b2);
    k_gram<<<2048, 256>>>();
    k_fin3<<<1, 64>>>(w3, g3, b3);
    k_final<<<4096, 256, 2 * 10816 * 4>>>(w3, fc_w, fc_b, out);
}

// round 4
// speedup vs baseline: 2.3987x; 2.2326x over previous
#include <cuda_runtime.h>
#include <cuda_fp16.h>

#define NPAIR 8192              // 16384 images as 8192 pairs

// Layouts (pair-interleaved, position-major):
//  g_h1: [pair][196][16][2] fp32  (205 MB)
//  g_h2: [pair][169][32][2] fp16  (177 MB)

__device__ float  g_h1[(size_t)NPAIR * 196 * 16 * 2];
__device__ __half g_h2[(size_t)NPAIR * 169 * 32 * 2];
__device__ float g_s1[32];      // sum[16], sumsq[16]
__device__ float g_s2[64];      // sum[32], sumsq[32]
__device__ float g_gram[1024];  // M[32][32]
__device__ float g_sumA[32];    // A[k]
__device__ float g_bn1[32];
__device__ float g_bn2[64];
__device__ float g_bn3[128];

// ---------------- f32x2 helpers ----------------
typedef unsigned long long ull;
__device__ __forceinline__ ull pk2(float a, float b) {
    ull r; asm("mov.b64 %0, {%1, %2};" : "=l"(r) : "f"(a), "f"(b)); return r;
}
__device__ __forceinline__ void upk2(ull v, float& a, float& b) {
    asm("mov.b64 {%0, %1}, %2;" : "=f"(a), "=f"(b) : "l"(v));
}
#define FMA2(d, a, b) asm("fma.rn.f32x2 %0, %1, %2, %0;" : "+l"(d) : "l"(a), "l"(b))

// ---------------- zero accumulators ----------------
__global__ void k_zero() {
    int t = threadIdx.x;
    g_gram[t] = 0.f;
    if (t < 32) { g_s1[t] = 0.f; g_sumA[t] = 0.f; }
    if (t < 64) g_s2[t] = 0.f;
}

// ---------------- conv1 (3x3) + stats1; output pair-packed fp32 ----------------
__global__ __launch_bounds__(256) void k_conv1(const float* __restrict__ x,
                                               const float* __restrict__ w1) {
    __shared__ float s_w[144];
    __shared__ float s_in[512];
    __shared__ float s_red[256];
    int t = threadIdx.x;
    if (t < 144) s_w[t] = w1[t];
    int c = t & 15, sel = (t >> 4) & 1, chunk = t >> 5;
    __syncthreads();
    const float* wc = &s_w[c * 9];
    float w00 = wc[0], w01 = wc[1], w02 = wc[2];
    float w10 = wc[3], w11 = wc[4], w12 = wc[5];
    float w20 = wc[6], w21 = wc[7], w22 = wc[8];
    float ls = 0.f, lsq = 0.f;
    int pair0 = blockIdx.x * 4;

    for (int pp = 0; pp < 4; pp++) {
        int pair = pair0 + pp;
        __syncthreads();
        const float* xp = x + (size_t)pair * 512;
        s_in[t] = xp[t];
        s_in[256 + t] = xp[256 + t];
        __syncthreads();
        const float* img = &s_in[sel * 256];
        float* dst = &g_h1[(size_t)pair * 6272];
        for (int p = chunk; p < 196; p += 8) {
            int y = p / 14, xx = p - y * 14;
            const float* r0 = &img[y * 16 + xx];
            float acc = r0[0]  * w00 + r0[1]  * w01 + r0[2]  * w02
                      + r0[16] * w10 + r0[17] * w11 + r0[18] * w12
                      + r0[32] * w20 + r0[33] * w21 + r0[34] * w22;
            dst[p * 32 + c * 2 + sel] = acc;
            ls += acc; lsq += acc * acc;
        }
    }
    __syncthreads();
    s_red[t] = ls;
    __syncthreads();
    if (t < 16) { float s = 0.f; for (int j = 0; j < 16; j++) s += s_red[t + 16 * j];
                  atomicAdd(&g_s1[t], s); }
    __syncthreads();
    s_red[t] = lsq;
    __syncthreads();
    if (t < 16) { float s = 0.f; for (int j = 0; j < 16; j++) s += s_red[t + 16 * j];
                  atomicAdd(&g_s1[16 + t], s); }
}

// ---------------- BN params for layers 1,2 ----------------
__global__ void k_finalize(int which, const float* __restrict__ gamma,
                           const float* __restrict__ beta) {
    int C     = (which == 0) ? 16 : 32;
    float* s  = (which == 0) ? g_s1 : g_s2;
    float* bn = (which == 0) ? g_bn1 : g_bn2;
    float n   = (which == 0) ? (16384.f * 196.f) : (16384.f * 169.f);
    int t = threadIdx.x;
    if (t < C) {
        float mean = s[t] / n;
        float var  = s[C + t] / n - mean * mean;
        float sc   = gamma[t] * rsqrtf(var + 1e-5f);
        bn[t] = sc;
        bn[C + t] = beta[t] - mean * sc;
    }
}

// ---------------- bn1+relu -> conv2 (2x2) + stats2; writes fp16 ----------------
__global__ __launch_bounds__(256) void k_conv2(const float* __restrict__ w2) {
    __shared__ __align__(16) float s_a[196 * 32];
    __shared__ float s_red[256];
    __shared__ float s_bn[32];
    int t = threadIdx.x;
    if (t < 32) s_bn[t] = g_bn1[t];
    int c2 = t & 31, chunk = t >> 5;
    float w[64];
    const float4* wsrc = reinterpret_cast<const float4*>(w2) + c2 * 16;
#pragma unroll
    for (int i = 0; i < 16; i++) {
        float4 v = wsrc[i];
        w[4 * i] = v.x; w[4 * i + 1] = v.y; w[4 * i + 2] = v.z; w[4 * i + 3] = v.w;
    }
    float ls = 0.f, lsq = 0.f;
    int pair0 = blockIdx.x * 4;

    for (int pp = 0; pp < 4; pp++) {
        int pair = pair0 + pp;
        __syncthreads();
        const float* src = &g_h1[(size_t)pair * 6272];
        for (int i = t; i < 6272; i += 256) {
            int c = (i >> 1) & 15;
            float v = src[i] * s_bn[c] + s_bn[16 + c];
            s_a[i] = v > 0.f ? v : 0.f;
        }
        __syncthreads();
        __half2* dst = reinterpret_cast<__half2*>(&g_h2[(size_t)pair * 10816]);
        for (int p = chunk; p < 169; p += 8) {
            int y = p / 13, xx = p - y * 13;
            const float4* r0 = reinterpret_cast<const float4*>(s_a) + (y * 14 + xx) * 8;
            const float4* r1 = r0 + 112;
            float a0 = 0.f, a1 = 0.f;
#pragma unroll
            for (int j = 0; j < 16; j++) {
                float4 v = r0[j];
                int c1 = (2 * j) & 15, kx = j >> 3;
                float wa = w[c1 * 4 + kx], wb = w[(c1 + 1) * 4 + kx];
                a0 += v.x * wa; a1 += v.y * wa;
                a0 += v.z * wb; a1 += v.w * wb;
            }
#pragma unroll
            for (int j = 0; j < 16; j++) {
                float4 v = r1[j];
                int c1 = (2 * j) & 15, kx = j >> 3;
                float wa = w[c1 * 4 + 2 + kx], wb = w[(c1 + 1) * 4 + 2 + kx];
                a0 += v.x * wa; a1 += v.y * wa;
                a0 += v.z * wb; a1 += v.w * wb;
            }
            dst[p * 32 + c2] = __floats2half2_rn(a0, a1);
            ls += a0 + a1; lsq += a0 * a0 + a1 * a1;
        }
    }
    __syncthreads();
    s_red[t] = ls;
    __syncthreads();
    if (t < 32) { float s = 0.f; for (int j = 0; j < 8; j++) s += s_red[t + 32 * j];
                  atomicAdd(&g_s2[t], s); }
    __syncthreads();
    s_red[t] = lsq;
    __syncthreads();
    if (t < 32) { float s = 0.f; for (int j = 0; j < 8; j++) s += s_red[t + 32 * j];
                  atomicAdd(&g_s2[32 + t], s); }
}

// ---------------- bn2+relu -> Gram of a2, 4x4 register tiles ----------------
__global__ __launch_bounds__(256) void k_gram() {
    __shared__ __align__(16) float s_a[169 * 64];   // [p][32ch][2img]
    __shared__ float s_bn[64];
    int t = threadIdx.x;
    if (t < 64) s_bn[t] = g_bn2[t];
    int slot = t >> 6;          // 4 position slots
    int idx = t & 63;
    int r4 = (idx >> 3) * 4;    // row block (0..28)
    int c4 = (idx & 7) * 4;     // col block (0..28)
    ull acc[4][4];
#pragma unroll
    for (int i = 0; i < 4; i++)
#pragma unroll
        for (int j = 0; j < 4; j++) acc[i][j] = pk2(0.f, 0.f);
    ull sA[4] = {pk2(0.f,0.f), pk2(0.f,0.f), pk2(0.f,0.f), pk2(0.f,0.f)};
    const ull one2 = pk2(1.f, 1.f);
    int pair0 = blockIdx.x * 4;

    for (int pp = 0; pp < 4; pp++) {
        __syncthreads();
        const __half2* src = reinterpret_cast<const __half2*>(&g_h2[(size_t)(pair0 + pp) * 10816]);
        for (int i = t; i < 169 * 32; i += 256) {
            float2 v = __half22float2(src[i]);
            int c = i & 31;
            float sc = s_bn[c], bi = s_bn[32 + c];
            s_a[2 * i]     = fmaxf(fmaf(v.x, sc, bi), 0.f);
            s_a[2 * i + 1] = fmaxf(fmaf(v.y, sc, bi), 0.f);
        }
        __syncthreads();
        const ulonglong2* ap = reinterpret_cast<const ulonglong2*>(s_a);  // 16 per row
        for (int p = slot; p < 169; p += 4) {
            ulonglong2 ra = ap[p * 16 + (r4 >> 1)];
            ulonglong2 rb = ap[p * 16 + (r4 >> 1) + 1];
            ulonglong2 ca = ap[p * 16 + (c4 >> 1)];
            ulonglong2 cb = ap[p * 16 + (c4 >> 1) + 1];
            ull rr[4] = {ra.x, ra.y, rb.x, rb.y};
            ull cc[4] = {ca.x, ca.y, cb.x, cb.y};
#pragma unroll
            for (int i = 0; i < 4; i++)
#pragma unroll
                for (int j = 0; j < 4; j++) FMA2(acc[i][j], rr[i], cc[j]);
            if (c4 == 0) {
#pragma unroll
                for (int i = 0; i < 4; i++) FMA2(sA[i], rr[i], one2);
            }
        }
    }
    float lo, hi;
#pragma unroll
    for (int i = 0; i < 4; i++)
#pragma unroll
        for (int j = 0; j < 4; j++) {
            upk2(acc[i][j], lo, hi);
            atomicAdd(&g_gram[(r4 + i) * 32 + c4 + j], lo + hi);
        }
    if (c4 == 0) {
#pragma unroll
        for (int i = 0; i < 4; i++) { upk2(sA[i], lo, hi); atomicAdd(&g_sumA[r4 + i], lo + hi); }
    }
}

// ---------------- bn3 params from Gram ----------------
__global__ void k_fin3(const float* __restrict__ w3, const float* __restrict__ gamma,
                       const float* __restrict__ beta) {
    __shared__ float s_m[1024];
    __shared__ float s_A[32];
    __shared__ float s_w[64 * 33];
    int t = threadIdx.x;    // 64 threads
    for (int i = t; i < 1024; i += 64) s_m[i] = g_gram[i];
    if (t < 32) s_A[t] = g_sumA[t];
    for (int kk = 0; kk < 32; kk++) s_w[t * 33 + kk] = w3[t * 32 + kk];
    __syncthreads();
    float S1 = 0.f, S2 = 0.f;
    for (int k = 0; k < 32; k++) {
        float wk = s_w[t * 33 + k];
        S1 += wk * s_A[k];
        float inner = 0.f;
        for (int kp = 0; kp < 32; kp++) inner += s_w[t * 33 + kp] * s_m[k * 32 + kp];
        S2 += wk * inner;
    }
    float n = 16384.f * 169.f;
    float mean = S1 / n;
    float var  = S2 / n - mean * mean;
    float sc   = gamma[t] * rsqrtf(var + 1e-5f);
    g_bn3[t] = sc;
    g_bn3[64 + t] = beta[t] - mean * sc;
}

// ---------------- bn2+relu -> conv3 -> bn3+relu -> fc, lanes-on-positions ----------------
// 1 pair per CTA, 192 threads (6 warps x 32 lanes = positions).
// a2 row (64 floats, img-pair packed) held in registers; w3 broadcast from SMEM
// duplicated-packed; fc_w loads are lane-coalesced in p (1 line per LDG).
#define FIN_THREADS 192
__global__ __launch_bounds__(FIN_THREADS) void k_final(const float* __restrict__ w3,
                                                       const float* __restrict__ fc_w,
                                                       const float* __restrict__ fc_b,
                                                       float* __restrict__ out) {
    extern __shared__ __align__(16) float sm[];
    float* s_a2 = sm;                 // [169][68] padded rows (stride 17 float4 = odd)
    float* s_wd = sm + 169 * 68;      // w3 duplicated: [c3][k][2] = 4096 floats
    __shared__ float s_bn2[64];
    __shared__ float s_bn3[128];
    __shared__ float s_out[20];
    int t = threadIdx.x;
    if (t < 64)  s_bn2[t] = g_bn2[t];
    if (t < 128) s_bn3[t] = g_bn3[t];
    if (t < 20)  s_out[t] = 0.f;
    for (int i = t; i < 2048; i += FIN_THREADS) {
        float w = w3[i];
        s_wd[2 * i] = w; s_wd[2 * i + 1] = w;
    }
    size_t pair = blockIdx.x;
    const __half2* src = reinterpret_cast<const __half2*>(&g_h2[pair * 10816]);
    __syncthreads();
    for (int i = t; i < 169 * 32; i += FIN_THREADS) {
        float2 v = __half22float2(src[i]);
        int c = i & 31, p = i >> 5;
        float sc = s_bn2[c], bi = s_bn2[32 + c];
        float2 o;
        o.x = fmaxf(fmaf(v.x, sc, bi), 0.f);
        o.y = fmaxf(fmaf(v.y, sc, bi), 0.f);
        *reinterpret_cast<float2*>(&s_a2[p * 68 + 2 * c]) = o;
    }
    __syncthreads();

    int lane = t & 31, wid = t >> 5;
    int p = wid * 32 + lane;
    int pc = p < 169 ? p : 168;

    ull a2r[32];
    {
        const ulonglong2* row = reinterpret_cast<const ulonglong2*>(&s_a2[pc * 68]);
#pragma unroll
        for (int i = 0; i < 16; i++) {
            ulonglong2 v = row[i];
            a2r[2 * i] = v.x; a2r[2 * i + 1] = v.y;
        }
    }
    ull o[10];
#pragma unroll
    for (int j = 0; j < 10; j++) o[j] = pk2(0.f, 0.f);

    for (int c3 = 0; c3 < 64; c3++) {
        const ulonglong2* wr = reinterpret_cast<const ulonglong2*>(&s_wd[c3 * 64]);
        ull acc0 = pk2(0.f, 0.f), acc1 = acc0;
#pragma unroll
        for (int i = 0; i < 16; i++) {
            ulonglong2 v = wr[i];
            FMA2(acc0, a2r[2 * i],     v.x);
            FMA2(acc1, a2r[2 * i + 1], v.y);
        }
        float e0, e1, f0, f1;
        upk2(acc0, e0, f0);
        upk2(acc1, e1, f1);
        float sc = s_bn3[c3], bi = s_bn3[64 + c3];
        float v0 = fmaxf(fmaf(e0 + e1, sc, bi), 0.f);   // image 0
        float v1 = fmaxf(fmaf(f0 + f1, sc, bi), 0.f);   // image 1
        ull v01 = pk2(v0, v1);
        const float* fw = &fc_w[c3 * 169 + pc];
#pragma unroll
        for (int j = 0; j < 10; j++) {
            float wv = __ldg(&fw[(size_t)j * 10816]);
            FMA2(o[j], v01, pk2(wv, wv));
        }
    }
    float o0[10], o1[10];
#pragma unroll
    for (int j = 0; j < 10; j++) {
        upk2(o[j], o0[j], o1[j]);
        if (p >= 169) { o0[j] = 0.f; o1[j] = 0.f; }
    }
#pragma unroll
    for (int j = 0; j < 10; j++)
#pragma unroll
        for (int off = 16; off > 0; off >>= 1) {
            o0[j] += __shfl_xor_sync(0xffffffffu, o0[j], off);
            o1[j] += __shfl_xor_sync(0xffffffffu, o1[j], off);
        }
    if (lane == 0) {
#pragma unroll
        for (int j = 0; j < 10; j++) {
            atomicAdd(&s_out[j],      o0[j]);
            atomicAdd(&s_out[10 + j], o1[j]);
        }
    }
    __syncthreads();
    if (t < 20) {
        int im = t / 10, j = t - im * 10;
        out[(pair * 2 + im) * 10 + j] = s_out[im * 10 + j] + fc_b[j];
    }
}

// ---------------- launch ----------------
extern "C" void kernel_launch(void* const* d_in, const int* in_sizes, int n_in,
                              void* d_out, int out_size) {
    const float* x    = (const float*)d_in[0];
    const float* w1   = (const float*)d_in[1];
    const float* w2   = (const float*)d_in[2];
    const float* w3   = (const float*)d_in[3];
    const float* g1   = (const float*)d_in[4];
    const float* b1   = (const float*)d_in[5];
    const float* g2   = (const float*)d_in[6];
    const float* b2   = (const float*)d_in[7];
    const float* g3   = (const float*)d_in[8];
    const float* b3   = (const float*)d_in[9];
    const float* fc_w = (const float*)d_in[10];
    const float* fc_b = (const float*)d_in[11];
    float* out = (float*)d_out;

    const int fin_smem = (169 * 68 + 4096) * 4;   // 62352 bytes
    cudaFuncSetAttribute(k_final, cudaFuncAttributeMaxDynamicSharedMemorySize, fin_smem);

    k_zero<<<1, 1024>>>();
    k_conv1<<<2048, 256>>>(x, w1);
    k_finalize<<<1, 64>>>(0, g1, b1);
    k_conv2<<<2048, 256>>>(w2);
    k_finalize<<<1, 64>>>(1, g2, b2);
    k_gram<<<2048, 256>>>();
    k_fin3<<<1, 64>>>(w3, g3, b3);
    k_final<<<NPAIR, FIN_THREADS, fin_smem>>>(w3, fc_w, fc_b, out);
}

// round 9
// speedup vs baseline: 2.5004x; 1.0424x over previous
#include <cuda_runtime.h>
#include <cuda_fp16.h>

#define NPAIR 8192              // 16384 images as 8192 pairs

// Layouts (pair-interleaved, position-major):
//  g_h1: [pair][196][16] half2  (102 MB)
//  g_h2: [pair][169][32] half2  (177 MB)

__device__ __half2 g_h1[(size_t)NPAIR * 196 * 16];
__device__ __half2 g_h2[(size_t)NPAIR * 169 * 32];
__device__ float g_fcwp[64 * 169 * 12];   // fc_w packed [c3][p][j(10)+pad2]
__device__ float g_s1[32];      // sum[16], sumsq[16]
__device__ float g_s2[64];      // sum[32], sumsq[32]
__device__ float g_gram[1024];  // M[32][32]
__device__ float g_sumA[32];    // A[k]
__device__ float g_bn1[32];
__device__ float g_bn2[64];
__device__ float g_bn3[128];

// ---------------- f32x2 helpers ----------------
typedef unsigned long long ull;
__device__ __forceinline__ ull pk2(float a, float b) {
    ull r; asm("mov.b64 %0, {%1, %2};" : "=l"(r) : "f"(a), "f"(b)); return r;
}
__device__ __forceinline__ void upk2(ull v, float& a, float& b) {
    asm("mov.b64 {%0, %1}, %2;" : "=f"(a), "=f"(b) : "l"(v));
}
#define FMA2(d, a, b) asm("fma.rn.f32x2 %0, %1, %2, %0;" : "+l"(d) : "l"(a), "l"(b))

// ---------------- zero accumulators ----------------
__global__ void k_zero() {
    int t = threadIdx.x;
    g_gram[t] = 0.f;
    if (t < 32) { g_s1[t] = 0.f; g_sumA[t] = 0.f; }
    if (t < 64) g_s2[t] = 0.f;
}

// ---------------- pack fc_w -> [c3][p][12] ----------------
__global__ void k_packfc(const float* __restrict__ fc_w) {
    int i = blockIdx.x * 256 + threadIdx.x;
    if (i >= 10816) return;           // i = c3*169 + p
#pragma unroll
    for (int j = 0; j < 10; j++) g_fcwp[i * 12 + j] = fc_w[(size_t)j * 10816 + i];
    g_fcwp[i * 12 + 10] = 0.f;
    g_fcwp[i * 12 + 11] = 0.f;
}

// ---------------- conv1 (3x3), both images per thread, fp16 out + stats1 ----------------
__global__ __launch_bounds__(256) void k_conv1(const float* __restrict__ x,
                                               const float* __restrict__ w1) {
    __shared__ float s_w[144];
    __shared__ float s_in[512];
    __shared__ float s_red[256];
    int t = threadIdx.x;
    if (t < 144) s_w[t] = w1[t];
    int c = t & 15, chunk = t >> 4;   // 16 chunks over 196 positions
    __syncthreads();
    const float* wc = &s_w[c * 9];
    float w00 = wc[0], w01 = wc[1], w02 = wc[2];
    float w10 = wc[3], w11 = wc[4], w12 = wc[5];
    float w20 = wc[6], w21 = wc[7], w22 = wc[8];
    float ls = 0.f, lsq = 0.f;
    int pair0 = blockIdx.x * 4;

    for (int pp = 0; pp < 4; pp++) {
        int pair = pair0 + pp;
        __syncthreads();
        const float* xp = x + (size_t)pair * 512;
        s_in[t] = xp[t];
        s_in[256 + t] = xp[256 + t];
        __syncthreads();
        __half2* dst = &g_h1[(size_t)pair * 3136];
        for (int p = chunk; p < 196; p += 16) {
            int y = p / 14, xx = p - y * 14;
            const float* r0 = &s_in[y * 16 + xx];
            const float* r1 = r0 + 256;
            float a0 = r0[0]  * w00 + r0[1]  * w01 + r0[2]  * w02
                     + r0[16] * w10 + r0[17] * w11 + r0[18] * w12
                     + r0[32] * w20 + r0[33] * w21 + r0[34] * w22;
            float a1 = r1[0]  * w00 + r1[1]  * w01 + r1[2]  * w02
                     + r1[16] * w10 + r1[17] * w11 + r1[18] * w12
                     + r1[32] * w20 + r1[33] * w21 + r1[34] * w22;
            __half2 hv = __floats2half2_rn(a0, a1);
            __stwt(&dst[p * 16 + c], hv);
            // stats on stored (rounded) values to match what conv2 consumes
            float b0 = __half2float(__low2half(hv));
            float b1 = __half2float(__high2half(hv));
            ls += b0 + b1; lsq += b0 * b0 + b1 * b1;
        }
    }
    __syncthreads();
    s_red[t] = ls;
    __syncthreads();
    if (t < 16) { float s = 0.f; for (int j = 0; j < 16; j++) s += s_red[t + 16 * j];
                  atomicAdd(&g_s1[t], s); }
    __syncthreads();
    s_red[t] = lsq;
    __syncthreads();
    if (t < 16) { float s = 0.f; for (int j = 0; j < 16; j++) s += s_red[t + 16 * j];
                  atomicAdd(&g_s1[16 + t], s); }
}

// ---------------- BN params for layers 1,2 ----------------
__global__ void k_finalize(int which, const float* __restrict__ gamma,
                           const float* __restrict__ beta) {
    int C     = (which == 0) ? 16 : 32;
    float* s  = (which == 0) ? g_s1 : g_s2;
    float* bn = (which == 0) ? g_bn1 : g_bn2;
    float n   = (which == 0) ? (16384.f * 196.f) : (16384.f * 169.f);
    int t = threadIdx.x;
    if (t < C) {
        float mean = s[t] / n;
        float var  = s[C + t] / n - mean * mean;
        float sc   = gamma[t] * rsqrtf(var + 1e-5f);
        bn[t] = sc;
        bn[C + t] = beta[t] - mean * sc;
    }
}

// ---------------- bn1+relu -> conv2 (2x2) via f32x2; fp16 out + stats2 ----------------
__global__ __launch_bounds__(256) void k_conv2(const float* __restrict__ w2) {
    __shared__ __align__(16) float s_a[196 * 32];   // [196][16ch][2img]
    __shared__ float s_red[256];
    __shared__ float s_bn[32];
    int t = threadIdx.x;
    if (t < 32) s_bn[t] = g_bn1[t];
    int c2 = t & 31, chunk = t >> 5;   // 8 chunks over 169 positions
    // 64 duplicated-packed weights in registers: wp[c1*4 + (ky*2+kx)]
    ull wp[64];
    {
        const float4* wsrc = reinterpret_cast<const float4*>(w2) + c2 * 16;
#pragma unroll
        for (int i = 0; i < 16; i++) {
            float4 v = wsrc[i];
            wp[4 * i]     = pk2(v.x, v.x);
            wp[4 * i + 1] = pk2(v.y, v.y);
            wp[4 * i + 2] = pk2(v.z, v.z);
            wp[4 * i + 3] = pk2(v.w, v.w);
        }
    }
    float ls = 0.f, lsq = 0.f;
    int pair0 = blockIdx.x * 4;

    for (int pp = 0; pp < 4; pp++) {
        int pair = pair0 + pp;
        __syncthreads();
        const __half2* src = &g_h1[(size_t)pair * 3136];
        for (int i = t; i < 3136; i += 256) {
            float2 v = __half22float2(src[i]);
            int c = i & 15;
            float sc = s_bn[c], bi = s_bn[16 + c];
            s_a[2 * i]     = fmaxf(fmaf(v.x, sc, bi), 0.f);
            s_a[2 * i + 1] = fmaxf(fmaf(v.y, sc, bi), 0.f);
        }
        __syncthreads();
        __half2* dst = reinterpret_cast<__half2*>(&g_h2[(size_t)pair * 5408]);
        const ulonglong2* ap2 = reinterpret_cast<const ulonglong2*>(s_a);  // 8 per position
        for (int p = chunk; p < 169; p += 8) {
            int y = p / 13, xx = p - y * 13;
            int r0 = (y * 14 + xx) * 8;       // ulonglong2 index of pos (y,xx)
            // 4 independent accumulator chains (8 deps each)
            ull acc0 = pk2(0.f, 0.f), acc1 = acc0, acc2 = acc0, acc3 = acc0;
#pragma unroll
            for (int h = 0; h < 8; h++) {     // c1 pair h -> channels 2h, 2h+1
                ulonglong2 A00 = ap2[r0 + h];
                ulonglong2 A01 = ap2[r0 + 8 + h];
                ulonglong2 A10 = ap2[r0 + 112 + h];
                ulonglong2 A11 = ap2[r0 + 120 + h];
                FMA2(acc0, A00.x, wp[8 * h]);     FMA2(acc1, A00.y, wp[8 * h + 4]);
                FMA2(acc2, A01.x, wp[8 * h + 1]); FMA2(acc3, A01.y, wp[8 * h + 5]);
                FMA2(acc0, A10.x, wp[8 * h + 2]); FMA2(acc1, A10.y, wp[8 * h + 6]);
                FMA2(acc2, A11.x, wp[8 * h + 3]); FMA2(acc3, A11.y, wp[8 * h + 7]);
            }
            float xa, xb, xc, xd, ya, yb, yc, yd;
            upk2(acc0, xa, ya); upk2(acc1, xb, yb);
            upk2(acc2, xc, yc); upk2(acc3, xd, yd);
            float a0 = (xa + xb) + (xc + xd);
            float a1 = (ya + yb) + (yc + yd);
            __half2 hv = __floats2half2_rn(a0, a1);
            dst[p * 32 + c2] = hv;
            // stats on rounded values (consistency with consumers)
            float b0 = __half2float(__low2half(hv));
            float b1 = __half2float(__high2half(hv));
            ls += b0 + b1; lsq += b0 * b0 + b1 * b1;
        }
    }
    __syncthreads();
    s_red[t] = ls;
    __syncthreads();
    if (t < 32) { float s = 0.f; for (int j = 0; j < 8; j++) s += s_red[t + 32 * j];
                  atomicAdd(&g_s2[t], s); }
    __syncthreads();
    s_red[t] = lsq;
    __syncthreads();
    if (t < 32) { float s = 0.f; for (int j = 0; j < 8; j++) s += s_red[t + 32 * j];
                  atomicAdd(&g_s2[32 + t], s); }
}

// ---------------- bn2+relu -> Gram of a2, 4x4 register tiles ----------------
__global__ __launch_bounds__(256) void k_gram() {
    __shared__ __align__(16) float s_a[169 * 64];   // [p][32ch][2img]
    __shared__ float s_bn[64];
    int t = threadIdx.x;
    if (t < 64) s_bn[t] = g_bn2[t];
    int slot = t >> 6;          // 4 position slots
    int idx = t & 63;
    int r4 = (idx >> 3) * 4;    // row block
    int c4 = (idx & 7) * 4;     // col block
    ull acc[4][4];
#pragma unroll
    for (int i = 0; i < 4; i++)
#pragma unroll
        for (int j = 0; j < 4; j++) acc[i][j] = pk2(0.f, 0.f);
    ull sA[4] = {pk2(0.f,0.f), pk2(0.f,0.f), pk2(0.f,0.f), pk2(0.f,0.f)};
    const ull one2 = pk2(1.f, 1.f);
    int pair0 = blockIdx.x * 4;

    for (int pp = 0; pp < 4; pp++) {
        __syncthreads();
        const __half2* src = &g_h2[(size_t)(pair0 + pp) * 5408];
        for (int i = t; i < 169 * 32; i += 256) {
            float2 v = __half22float2(src[i]);
            int c = i & 31;
            float sc = s_bn[c], bi = s_bn[32 + c];
            s_a[2 * i]     = fmaxf(fmaf(v.x, sc, bi), 0.f);
            s_a[2 * i + 1] = fmaxf(fmaf(v.y, sc, bi), 0.f);
        }
        __syncthreads();
        const ulonglong2* ap = reinterpret_cast<const ulonglong2*>(s_a);
        for (int p = slot; p < 169; p += 4) {
            ulonglong2 ra = ap[p * 16 + (r4 >> 1)];
            ulonglong2 rb = ap[p * 16 + (r4 >> 1) + 1];
            ulonglong2 ca = ap[p * 16 + (c4 >> 1)];
            ulonglong2 cb = ap[p * 16 + (c4 >> 1) + 1];
            ull rr[4] = {ra.x, ra.y, rb.x, rb.y};
            ull cc[4] = {ca.x, ca.y, cb.x, cb.y};
#pragma unroll
            for (int i = 0; i < 4; i++)
#pragma unroll
                for (int j = 0; j < 4; j++) FMA2(acc[i][j], rr[i], cc[j]);
            if (c4 == 0) {
#pragma unroll
                for (int i = 0; i < 4; i++) FMA2(sA[i], rr[i], one2);
            }
        }
    }
    float lo, hi;
#pragma unroll
    for (int i = 0; i < 4; i++)
#pragma unroll
        for (int j = 0; j < 4; j++) {
            upk2(acc[i][j], lo, hi);
            atomicAdd(&g_gram[(r4 + i) * 32 + c4 + j], lo + hi);
        }
    if (c4 == 0) {
#pragma unroll
        for (int i = 0; i < 4; i++) { upk2(sA[i], lo, hi); atomicAdd(&g_sumA[r4 + i], lo + hi); }
    }
}

// ---------------- bn3 params from Gram ----------------
__global__ void k_fin3(const float* __restrict__ w3, const float* __restrict__ gamma,
                       const float* __restrict__ beta) {
    __shared__ float s_m[1024];
    __shared__ float s_A[32];
    __shared__ float s_w[64 * 33];
    int t = threadIdx.x;    // 64 threads
    for (int i = t; i < 1024; i += 64) s_m[i] = g_gram[i];
    if (t < 32) s_A[t] = g_sumA[t];
    for (int kk = 0; kk < 32; kk++) s_w[t * 33 + kk] = w3[t * 32 + kk];
    __syncthreads();
    float S1 = 0.f, S2 = 0.f;
    for (int k = 0; k < 32; k++) {
        float wk = s_w[t * 33 + k];
        S1 += wk * s_A[k];
        float inner = 0.f;
        for (int kp = 0; kp < 32; kp++) inner += s_w[t * 33 + kp] * s_m[k * 32 + kp];
        S2 += wk * inner;
    }
    float n = 16384.f * 169.f;
    float mean = S1 / n;
    float var  = S2 / n - mean * mean;
    float sc   = gamma[t] * rsqrtf(var + 1e-5f);
    g_bn3[t] = sc;
    g_bn3[64 + t] = beta[t] - mean * sc;
}

// ---------------- bn2+relu -> conv3 (f32x2) -> bn3+relu -> fc (packed fcw) ----------------
#define FIN_THREADS 192
__global__ __launch_bounds__(FIN_THREADS) void k_final(const float* __restrict__ w3,
                                                       const float* __restrict__ fc_b,
                                                       float* __restrict__ out) {
    extern __shared__ __align__(16) float sm[];
    float* s_a2 = sm;                 // [169][68] padded rows
    float* s_wd = sm + 169 * 68;      // w3 duplicated: [c3][k][2]
    __shared__ float s_bn2[64];
    __shared__ float s_bn3[128];
    __shared__ float s_out[20];
    int t = threadIdx.x;
    if (t < 64)  s_bn2[t] = g_bn2[t];
    if (t < 128) s_bn3[t] = g_bn3[t];
    if (t < 20)  s_out[t] = 0.f;
    for (int i = t; i < 2048; i += FIN_THREADS) {
        float w = w3[i];
        s_wd[2 * i] = w; s_wd[2 * i + 1] = w;
    }
    size_t pair = blockIdx.x;
    const __half2* src = &g_h2[pair * 5408];
    __syncthreads();
    for (int i = t; i < 169 * 32; i += FIN_THREADS) {
        float2 v = __half22float2(src[i]);
        int c = i & 31, p = i >> 5;
        float sc = s_bn2[c], bi = s_bn2[32 + c];
        float2 o;
        o.x = fmaxf(fmaf(v.x, sc, bi), 0.f);
        o.y = fmaxf(fmaf(v.y, sc, bi), 0.f);
        *reinterpret_cast<float2*>(&s_a2[p * 68 + 2 * c]) = o;
    }
    __syncthreads();

    int lane = t & 31, wid = t >> 5;
    int p = wid * 32 + lane;
    int pc = p < 169 ? p : 168;

    ull a2r[32];
    {
        const ulonglong2* row = reinterpret_cast<const ulonglong2*>(&s_a2[pc * 68]);
#pragma unroll
        for (int i = 0; i < 16; i++) {
            ulonglong2 v = row[i];
            a2r[2 * i] = v.x; a2r[2 * i + 1] = v.y;
        }
    }
    float o0[10], o1[10];
#pragma unroll
    for (int j = 0; j < 10; j++) { o0[j] = 0.f; o1[j] = 0.f; }
    const float4* fwp = reinterpret_cast<const float4*>(g_fcwp);

    for (int c3 = 0; c3 < 64; c3++) {
        const ulonglong2* wr = reinterpret_cast<const ulonglong2*>(&s_wd[c3 * 64]);
        // 4 independent chains of 8 deps
        ull acc0 = pk2(0.f, 0.f), acc1 = acc0, acc2 = acc0, acc3 = acc0;
#pragma unroll
        for (int i = 0; i < 8; i++) {
            ulonglong2 va = wr[2 * i];
            ulonglong2 vb = wr[2 * i + 1];
            FMA2(acc0, a2r[4 * i],     va.x);
            FMA2(acc1, a2r[4 * i + 1], va.y);
            FMA2(acc2, a2r[4 * i + 2], vb.x);
            FMA2(acc3, a2r[4 * i + 3], vb.y);
        }
        float e0, e1, e2, e3, f0, f1, f2, f3;
        upk2(acc0, e0, f0);
        upk2(acc1, e1, f1);
        upk2(acc2, e2, f2);
        upk2(acc3, e3, f3);
        float sc = s_bn3[c3], bi = s_bn3[64 + c3];
        float v0 = fmaxf(fmaf((e0 + e1) + (e2 + e3), sc, bi), 0.f);   // image 0
        float v1 = fmaxf(fmaf((f0 + f1) + (f2 + f3), sc, bi), 0.f);   // image 1
        int base = (c3 * 169 + pc) * 3;
        float4 w0 = fwp[base], w1 = fwp[base + 1], w2 = fwp[base + 2];
        o0[0] += v0 * w0.x; o1[0] += v1 * w0.x;
        o0[1] += v0 * w0.y; o1[1] += v1 * w0.y;
        o0[2] += v0 * w0.z; o1[2] += v1 * w0.z;
        o0[3] += v0 * w0.w; o1[3] += v1 * w0.w;
        o0[4] += v0 * w1.x; o1[4] += v1 * w1.x;
        o0[5] += v0 * w1.y; o1[5] += v1 * w1.y;
        o0[6] += v0 * w1.z; o1[6] += v1 * w1.z;
        o0[7] += v0 * w1.w; o1[7] += v1 * w1.w;
        o0[8] += v0 * w2.x; o1[8] += v1 * w2.x;
        o0[9] += v0 * w2.y; o1[9] += v1 * w2.y;
    }
#pragma unroll
    for (int j = 0; j < 10; j++) {
        if (p >= 169) { o0[j] = 0.f; o1[j] = 0.f; }
#pragma unroll
        for (int off = 16; off > 0; off >>= 1) {
            o0[j] += __shfl_xor_sync(0xffffffffu, o0[j], off);
            o1[j] += __shfl_xor_sync(0xffffffffu, o1[j], off);
        }
    }
    if (lane == 0) {
#pragma unroll
        for (int j = 0; j < 10; j++) {
            atomicAdd(&s_out[j],      o0[j]);
            atomicAdd(&s_out[10 + j], o1[j]);
        }
    }
    __syncthreads();
    if (t < 20) {
        int im = t / 10, j = t - im * 10;
        out[(pair * 2 + im) * 10 + j] = s_out[im * 10 + j] + fc_b[j];
    }
}

// ---------------- launch ----------------
extern "C" void kernel_launch(void* const* d_in, const int* in_sizes, int n_in,
                              void* d_out, int out_size) {
    const float* x    = (const float*)d_in[0];
    const float* w1   = (const float*)d_in[1];
    const float* w2   = (const float*)d_in[2];
    const float* w3   = (const float*)d_in[3];
    const float* g1   = (const float*)d_in[4];
    const float* b1   = (const float*)d_in[5];
    const float* g2   = (const float*)d_in[6];
    const float* b2   = (const float*)d_in[7];
    const float* g3   = (const float*)d_in[8];
    const float* b3   = (const float*)d_in[9];
    const float* fc_w = (const float*)d_in[10];
    const float* fc_b = (const float*)d_in[11];
    float* out = (float*)d_out;

    const int fin_smem = (169 * 68 + 4096) * 4;   // 62352 bytes
    cudaFuncSetAttribute(k_final, cudaFuncAttributeMaxDynamicSharedMemorySize, fin_smem);

    k_zero<<<1, 1024>>>();
    k_packfc<<<43, 256>>>(fc_w);
    k_conv1<<<2048, 256>>>(x, w1);
    k_finalize<<<1, 64>>>(0, g1, b1);
    k_conv2<<<2048, 256>>>(w2);
    k_finalize<<<1, 64>>>(1, g2, b2);
    k_gram<<<2048, 256>>>();
    k_fin3<<<1, 64>>>(w3, g3, b3);
    k_final<<<NPAIR, FIN_THREADS, fin_smem>>>(w3, fc_b, out);
}